// round 9
// baseline (speedup 1.0000x reference)
#include <cuda_runtime.h>
#include <math.h>

#define NTOK 8192
#define HDIM 4096
#define NOUT 12       // M_ANCH * (D+1)
#define NANCH 4
#define KOUT 16
#define SMEM_BYTES (NOUT * HDIM * 4)   // 196608

// cublasLt splitK=2: K split into 2 contiguous chunks of 2048, each chunk a
// from-zero sequential ascending-k fma chain, partials folded s0+s1.
#define NCHUNK 2
#define CHUNK_F4 (HDIM / 4 / NCHUNK)   // 512 float4 per chunk

// libdevice exp (what XLA:GPU emits for exp).
extern "C" __device__ float __nv_expf(float);

// scratch: logits[NTOK][NOUT]
__device__ float g_logits[NTOK * NOUT];

// ---------------------------------------------------------------------------
// XLA f32 tanh: rational polynomial (EmitFastTanh), bit-exact.
// ---------------------------------------------------------------------------
__device__ __forceinline__ float xla_tanhf(float x) {
    const float plus_clamp = 7.90531110763549805f;
    const float ax = fabsf(x);
    const float xc = fmaxf(fminf(x, plus_clamp), -plus_clamp);
    const float x2 = __fmul_rn(xc, xc);
    float p = fmaf(x2, -2.76076847742355e-16f, 2.00018790482477e-13f);
    p = fmaf(x2, p, -8.60467152213735e-11f);
    p = fmaf(x2, p, 5.12229709037114e-08f);
    p = fmaf(x2, p, 1.48572235717979e-05f);
    p = fmaf(x2, p, 6.37261928875436e-04f);
    p = fmaf(x2, p, 4.89352455891786e-03f);
    p = __fmul_rn(xc, p);
    float q = fmaf(x2, 1.19825839466702e-06f, 1.18534705686654e-04f);
    q = fmaf(x2, q, 2.26843463243900e-03f);
    q = fmaf(x2, q, 4.89352518554385e-03f);
    return (ax < 0.0004f) ? x : __fdiv_rn(p, q);
}
__device__ __forceinline__ float xla_sigmoidf(float x) {
    const float t = xla_tanhf(__fmul_rn(0.5f, x));
    return __fadd_rn(__fmul_rn(0.5f, t), 0.5f);
}

// ---------------------------------------------------------------------------
// Kernel 1: logits = hidden @ W.T + b. cublasLt splitK=2 order: 2 contiguous
// K-chunks of 2048, each a from-zero sequential ascending-k fused-fma chain,
// partials folded s0+s1, bias added last.
// 2 threads per token, each owning 6 of 12 outputs via packed fma.rn.f32x2
// (IEEE round-to-nearest per lane == two independent fmaf chains).
// ---------------------------------------------------------------------------
__device__ __forceinline__ void fma_step(float h, unsigned addr,
                                         unsigned long long& a0,
                                         unsigned long long& a1,
                                         unsigned long long& a2) {
    asm("{\n\t"
        ".reg .b64 hd, w0, w1, w2;\n\t"
        "mov.b64 hd, {%3, %3};\n\t"
        "ld.shared.b64 w0, [%4];\n\t"
        "ld.shared.b64 w1, [%4+8];\n\t"
        "ld.shared.b64 w2, [%4+16];\n\t"
        "fma.rn.f32x2 %0, hd, w0, %0;\n\t"
        "fma.rn.f32x2 %1, hd, w1, %1;\n\t"
        "fma.rn.f32x2 %2, hd, w2, %2;\n\t"
        "}"
        : "+l"(a0), "+l"(a1), "+l"(a2)
        : "f"(h), "r"(addr));
}
__device__ __forceinline__ void acc_add(unsigned long long& tot,
                                        unsigned long long acc) {
    asm("add.rn.f32x2 %0, %0, %1;" : "+l"(tot) : "l"(acc));
}

__global__ __launch_bounds__(128, 1)
void logits_split2_kernel(const float* __restrict__ hidden,
                          const float* __restrict__ W,
                          const float* __restrict__ b) {
    extern __shared__ float ws[];   // [HDIM][12], 48 bytes per k-row
    for (int i = threadIdx.x; i < NOUT * HDIM; i += 128) {
        const int j = i >> 12;            // row of W (output index)
        const int k = i & (HDIM - 1);
        ws[k * NOUT + j] = W[i];
    }
    __syncthreads();

    const int jh    = threadIdx.x & 1;                   // which 6 outputs
    const int token = blockIdx.x * 64 + (threadIdx.x >> 1);
    unsigned sa = (unsigned)__cvta_generic_to_shared(ws) + jh * 24;

    const float4* h4 = (const float4*)hidden + (size_t)token * (HDIM / 4);

    unsigned long long t0 = 0ull, t1 = 0ull, t2 = 0ull;  // running fold

    int kk = 0;                        // float4 index (4 k per step)
    for (int c = 0; c < NCHUNK; ++c) {
        unsigned long long a0 = 0ull, a1 = 0ull, a2 = 0ull;
        for (int itr = 0; itr < CHUNK_F4 / 16; ++itr) {
            float4 hb[16];
#pragma unroll
            for (int u = 0; u < 16; ++u) hb[u] = h4[kk + u];
            const unsigned ga = sa + (unsigned)kk * 192;  // 48 B per k
#pragma unroll
            for (int u = 0; u < 16; ++u) {
                fma_step(hb[u].x, ga + u * 192 +   0, a0, a1, a2);
                fma_step(hb[u].y, ga + u * 192 +  48, a0, a1, a2);
                fma_step(hb[u].z, ga + u * 192 +  96, a0, a1, a2);
                fma_step(hb[u].w, ga + u * 192 + 144, a0, a1, a2);
            }
            kk += 16;
        }
        acc_add(t0, a0); acc_add(t1, a1); acc_add(t2, a2);
    }

    float r[6];
    r[0] = __uint_as_float((unsigned)(t0 & 0xffffffffull));
    r[1] = __uint_as_float((unsigned)(t0 >> 32));
    r[2] = __uint_as_float((unsigned)(t1 & 0xffffffffull));
    r[3] = __uint_as_float((unsigned)(t1 >> 32));
    r[4] = __uint_as_float((unsigned)(t2 & 0xffffffffull));
    r[5] = __uint_as_float((unsigned)(t2 >> 32));

    const int obase = token * NOUT + jh * 6;
#pragma unroll
    for (int i = 0; i < 6; ++i)
        g_logits[obase + i] = __fadd_rn(r[i], b[jh * 6 + i]);
}

// ---------------------------------------------------------------------------
// Kernel 2: per-token routing epilogue. One warp per token.
// ---------------------------------------------------------------------------
__device__ __forceinline__ unsigned int ford(float v) {
    unsigned int u = __float_as_uint(v);
    return (u & 0x80000000u) ? ~u : (u | 0x80000000u);
}

__global__ __launch_bounds__(256, 8)
void route_kernel(float* __restrict__ out) {
    const int lane  = threadIdx.x & 31;
    const int token = blockIdx.x * (blockDim.x >> 5) + (threadIdx.x >> 5);
    if (token >= NTOK) return;

    float lg = 0.f;
    if (lane < NOUT) lg = g_logits[token * NOUT + lane];
    float L[NOUT];
#pragma unroll
    for (int i = 0; i < NOUT; ++i) L[i] = __shfl_sync(0xffffffffu, lg, i);

    // anchor softmax over L[2], L[5], L[8], L[11]
    float pi[NANCH];
    {
        const float m = fmaxf(fmaxf(L[2], L[5]), fmaxf(L[8], L[11]));
        const float e0 = __nv_expf(__fadd_rn(L[2], -m));
        const float e1 = __nv_expf(__fadd_rn(L[5], -m));
        const float e2 = __nv_expf(__fadd_rn(L[8], -m));
        const float e3 = __nv_expf(__fadd_rn(L[11], -m));
        const float s = __fadd_rn(__fadd_rn(__fadd_rn(e0, e1), e2), e3);
        pi[0] = __fdiv_rn(e0, s); pi[1] = __fdiv_rn(e1, s);
        pi[2] = __fdiv_rn(e2, s); pi[3] = __fdiv_rn(e3, s);
    }

    float v0 = 0.f, v1 = 0.f;   // my two cells: lane, lane+32

#pragma unroll
    for (int a = 0; a < NANCH; ++a) {
        float fr[2]; int ai[2];
#pragma unroll
        for (int d = 0; d < 2; ++d) {
            const float x = L[a * 3 + d];
            float u = xla_sigmoidf(x);
            u = fminf(fmaxf(u, 1e-6f), 1.0f - 1e-6f);
            float p = __fmul_rn(u, 7.0f);
            p = fminf(p, 7.0f - 1e-6f);
            p = fmaxf(p, 0.f);
            int aa = (int)floorf(p);
            aa = max(0, min(aa, 6));
            float f = __fadd_rn(p, -(float)aa);
            f = fminf(fmaxf(f, 1e-6f), 1.0f - 1e-6f);
            fr[d] = f; ai[d] = aa;
        }
        const float om0 = __fadd_rn(1.0f, -fr[0]);
        const float om1 = __fadd_rn(1.0f, -fr[1]);
        float w[4];
        w[0] = __fmul_rn(om0,   om1);
        w[1] = __fmul_rn(fr[0], om1);
        w[2] = __fmul_rn(om0,   fr[1]);
        w[3] = __fmul_rn(fr[0], fr[1]);
        const float ws = __fadd_rn(__fadd_rn(__fadd_rn(w[0], w[1]), w[2]), w[3]);
        const float denom = __fadd_rn(ws, 1e-9f);
#pragma unroll
        for (int t = 0; t < 4; ++t) {
            const int c0 = ai[0] + (t & 1);
            const int c1 = ai[1] + ((t >> 1) & 1);
            const int idx = c0 + (c1 << 3);
            const float wv = __fmul_rn(__fdiv_rn(w[t], denom), pi[a]);
            if (idx == lane)      v0 = __fadd_rn(v0, wv);
            if (idx == lane + 32) v1 = __fadd_rn(v1, wv);
        }
    }

    // normalize by grid sum (common denominator: cannot flip ranks)
    float s = __fadd_rn(v0, v1);
    s = __fadd_rn(s, __shfl_xor_sync(0xffffffffu, s, 16));
    s = __fadd_rn(s, __shfl_xor_sync(0xffffffffu, s, 8));
    s = __fadd_rn(s, __shfl_xor_sync(0xffffffffu, s, 4));
    s = __fadd_rn(s, __shfl_xor_sync(0xffffffffu, s, 2));
    s = __fadd_rn(s, __shfl_xor_sync(0xffffffffu, s, 1));
    const float dn = __fadd_rn(s, 1e-9f);
    v0 = __fdiv_rn(v0, dn);
    v1 = __fdiv_rn(v1, dn);

    float* out_idx = out + (size_t)token * KOUT;
    float* out_w   = out + (size_t)NTOK * KOUT + (size_t)token * KOUT;

    for (int r = 0; r < KOUT; ++r) {
        unsigned long long k0 =
            ((unsigned long long)ford(v0) << 32) | (unsigned int)(63 - lane);
        unsigned long long k1 =
            ((unsigned long long)ford(v1) << 32) | (unsigned int)(63 - (lane + 32));
        unsigned long long k = (k0 > k1) ? k0 : k1;
#pragma unroll
        for (int sft = 16; sft > 0; sft >>= 1) {
            unsigned long long o = __shfl_xor_sync(0xffffffffu, k, sft);
            if (o > k) k = o;
        }
        const int cell = 63 - (int)(k & 63ull);
        const unsigned int ou = (unsigned int)(k >> 32);
        const float val =
            __uint_as_float((ou & 0x80000000u) ? (ou ^ 0x80000000u) : ~ou);
        if (lane == 0) {
            out_idx[r] = (float)cell;
            out_w[r]   = val;
        }
        if (cell == lane)      v0 = -1.0f;
        if (cell == lane + 32) v1 = -1.0f;
    }
}

// ---------------------------------------------------------------------------
extern "C" void kernel_launch(void* const* d_in, const int* in_sizes, int n_in,
                              void* d_out, int out_size) {
    const float* hidden = nullptr;
    const float* W = nullptr;
    const float* b = nullptr;
    for (int i = 0; i < n_in; ++i) {
        if (in_sizes[i] == NTOK * HDIM)      hidden = (const float*)d_in[i];
        else if (in_sizes[i] == NOUT * HDIM) W = (const float*)d_in[i];
        else if (in_sizes[i] == NOUT)        b = (const float*)d_in[i];
    }
    (void)out_size;

    cudaFuncSetAttribute(logits_split2_kernel,
                         cudaFuncAttributeMaxDynamicSharedMemorySize, SMEM_BYTES);
    logits_split2_kernel<<<NTOK * 2 / 128, 128, SMEM_BYTES>>>(hidden, W, b);
    route_kernel<<<NTOK / 8, 256>>>((float*)d_out);
}

// round 10
// speedup vs baseline: 1.9219x; 1.9219x over previous
#include <cuda_runtime.h>
#include <math.h>

#define NTOK 8192
#define HDIM 4096
#define NOUT 12       // M_ANCH * (D+1)
#define NANCH 4
#define KOUT 16

// GEMM decomposition (rounding-order-mandated): 2 contiguous chunks of 2048.
#define KC 2048
#define HT 32                     // k per hidden tile
#define NT (KC / HT)              // 64 tiles
#define TOKB 64                   // tokens per block
#define TPB 128                   // threads per block (2 per token)
#define ROWB 136                  // bytes per hidden smem row (34 floats, padded)
#define W_BYTES (KC * 12 * 4)     // 98304
#define HT_BYTES (TOKB * ROWB)    // 8704
#define SMEM_TOTAL (W_BYTES + 2 * HT_BYTES)  // 115712 -> 2 blocks/SM

// libdevice exp (what XLA:GPU emits for exp).
extern "C" __device__ float __nv_expf(float);

// chunk partial sums: g_part[chunk][token][j]
__device__ float g_part[2][NTOK][NOUT];

// ---------------------------------------------------------------------------
// XLA f32 tanh: rational polynomial (EmitFastTanh), bit-exact.
// ---------------------------------------------------------------------------
__device__ __forceinline__ float xla_tanhf(float x) {
    const float plus_clamp = 7.90531110763549805f;
    const float ax = fabsf(x);
    const float xc = fmaxf(fminf(x, plus_clamp), -plus_clamp);
    const float x2 = __fmul_rn(xc, xc);
    float p = fmaf(x2, -2.76076847742355e-16f, 2.00018790482477e-13f);
    p = fmaf(x2, p, -8.60467152213735e-11f);
    p = fmaf(x2, p, 5.12229709037114e-08f);
    p = fmaf(x2, p, 1.48572235717979e-05f);
    p = fmaf(x2, p, 6.37261928875436e-04f);
    p = fmaf(x2, p, 4.89352455891786e-03f);
    p = __fmul_rn(xc, p);
    float q = fmaf(x2, 1.19825839466702e-06f, 1.18534705686654e-04f);
    q = fmaf(x2, q, 2.26843463243900e-03f);
    q = fmaf(x2, q, 4.89352518554385e-03f);
    return (ax < 0.0004f) ? x : __fdiv_rn(p, q);
}
__device__ __forceinline__ float xla_sigmoidf(float x) {
    const float t = xla_tanhf(__fmul_rn(0.5f, x));
    return __fadd_rn(__fmul_rn(0.5f, t), 0.5f);
}

// ---------------------------------------------------------------------------
// Identical fused-fma chain step as the passing kernel (bit-exact order).
// ---------------------------------------------------------------------------
__device__ __forceinline__ void fma_step(float h, unsigned addr,
                                         unsigned long long& a0,
                                         unsigned long long& a1,
                                         unsigned long long& a2) {
    asm("{\n\t"
        ".reg .b64 hd, w0, w1, w2;\n\t"
        "mov.b64 hd, {%3, %3};\n\t"
        "ld.shared.b64 w0, [%4];\n\t"
        "ld.shared.b64 w1, [%4+8];\n\t"
        "ld.shared.b64 w2, [%4+16];\n\t"
        "fma.rn.f32x2 %0, hd, w0, %0;\n\t"
        "fma.rn.f32x2 %1, hd, w1, %1;\n\t"
        "fma.rn.f32x2 %2, hd, w2, %2;\n\t"
        "}"
        : "+l"(a0), "+l"(a1), "+l"(a2)
        : "f"(h), "r"(addr));
}

// ---------------------------------------------------------------------------
// Kernel 1: per-chunk partial logits. Hidden staged through smem with
// coalesced cp.async (fixes the 32-lines-per-warp-LDG disaster); W chunk
// k-major in smem. The per-(token,output) fma chain over ascending k within
// the chunk is UNCHANGED -> bit-exact vs the passing kernel.
// ---------------------------------------------------------------------------
__global__ __launch_bounds__(TPB, 2)
void logits_chunk_kernel(const float* __restrict__ hidden,
                         const float* __restrict__ W) {
    extern __shared__ float sm[];
    const int tid   = threadIdx.x;
    const int chunk = blockIdx.y;
    const int kc    = chunk * KC;
    const int tok0  = blockIdx.x * TOKB;

    const unsigned sbase = (unsigned)__cvta_generic_to_shared(sm);
    const unsigned ht0   = sbase + W_BYTES;

    // stage tile 0 (async) before W preload so both overlap
#pragma unroll
    for (int r = 0; r < 8; ++r) {
        const int s = tid + r * TPB;          // 0..1023 8B segments
        const int tok = s >> 4, sk = s & 15;  // 16 segs of 8B = 128B row
        const float* src = hidden + (size_t)(tok0 + tok) * HDIM + kc + sk * 2;
        const unsigned dst = ht0 + tok * ROWB + sk * 8;
        asm volatile("cp.async.ca.shared.global [%0], [%1], 8;"
                     :: "r"(dst), "l"(src));
    }
    asm volatile("cp.async.commit_group;");

    // W chunk preload: smem ws[k][12], coalesced global reads per j-row
    for (int i = tid; i < KC * 12; i += TPB) {
        const int j = i >> 11;                // 0..11
        const int k = i & (KC - 1);
        sm[k * 12 + j] = W[j * HDIM + kc + k];
    }

    const int jh = tid & 1;
    const int lt = tid >> 1;                  // local token
    unsigned wk = sbase + jh * 24;            // W addr, +48B per k
    const unsigned hrow = ht0 + lt * ROWB;

    unsigned long long a0 = 0ull, a1 = 0ull, a2 = 0ull;

    for (int t = 0; t < NT; ++t) {
        if (t + 1 < NT) {
#pragma unroll
            for (int r = 0; r < 8; ++r) {
                const int s = tid + r * TPB;
                const int tok = s >> 4, sk = s & 15;
                const float* src = hidden + (size_t)(tok0 + tok) * HDIM
                                 + kc + (t + 1) * HT + sk * 2;
                const unsigned dst = ht0 + ((t + 1) & 1) * HT_BYTES
                                   + tok * ROWB + sk * 8;
                asm volatile("cp.async.ca.shared.global [%0], [%1], 8;"
                             :: "r"(dst), "l"(src));
            }
            asm volatile("cp.async.commit_group;");
            asm volatile("cp.async.wait_group 1;");
        } else {
            asm volatile("cp.async.wait_group 0;");
        }
        __syncthreads();   // tile (t&1) ready in all lanes; also covers W preload at t=0

        const unsigned hb = hrow + (t & 1) * HT_BYTES;
#pragma unroll
        for (int kk = 0; kk < HT; kk += 2) {
            float hx, hy;
            asm("ld.shared.v2.f32 {%0,%1}, [%2];"
                : "=f"(hx), "=f"(hy) : "r"(hb + kk * 4));
            fma_step(hx, wk, a0, a1, a2);
            fma_step(hy, wk + 48, a0, a1, a2);
            wk += 96;
        }
        __syncthreads();   // protect buffer (t&1) before it is re-staged
    }

    float r[6];
    r[0] = __uint_as_float((unsigned)(a0 & 0xffffffffull));
    r[1] = __uint_as_float((unsigned)(a0 >> 32));
    r[2] = __uint_as_float((unsigned)(a1 & 0xffffffffull));
    r[3] = __uint_as_float((unsigned)(a1 >> 32));
    r[4] = __uint_as_float((unsigned)(a2 & 0xffffffffull));
    r[5] = __uint_as_float((unsigned)(a2 >> 32));

    const int gt = tok0 + lt;
#pragma unroll
    for (int i = 0; i < 6; ++i)
        g_part[chunk][gt][jh * 6 + i] = r[i];
}

// ---------------------------------------------------------------------------
// Kernel 2: per-token routing epilogue (one warp per token), unchanged except
// it now folds the chunk partials itself: L = ((0+p0)+p1)+b — the exact
// rounding sequence of the passing kernel.
// ---------------------------------------------------------------------------
__device__ __forceinline__ unsigned int ford(float v) {
    unsigned int u = __float_as_uint(v);
    return (u & 0x80000000u) ? ~u : (u | 0x80000000u);
}

__global__ __launch_bounds__(256, 8)
void route_kernel(const float* __restrict__ b, float* __restrict__ out) {
    const int lane  = threadIdx.x & 31;
    const int token = blockIdx.x * (blockDim.x >> 5) + (threadIdx.x >> 5);
    if (token >= NTOK) return;

    float lg = 0.f;
    if (lane < NOUT) {
        const float p0 = g_part[0][token][lane];
        const float p1 = g_part[1][token][lane];
        lg = __fadd_rn(__fadd_rn(__fadd_rn(0.0f, p0), p1), b[lane]);
    }
    float L[NOUT];
#pragma unroll
    for (int i = 0; i < NOUT; ++i) L[i] = __shfl_sync(0xffffffffu, lg, i);

    // anchor softmax over L[2], L[5], L[8], L[11]
    float pi[NANCH];
    {
        const float m = fmaxf(fmaxf(L[2], L[5]), fmaxf(L[8], L[11]));
        const float e0 = __nv_expf(__fadd_rn(L[2], -m));
        const float e1 = __nv_expf(__fadd_rn(L[5], -m));
        const float e2 = __nv_expf(__fadd_rn(L[8], -m));
        const float e3 = __nv_expf(__fadd_rn(L[11], -m));
        const float s = __fadd_rn(__fadd_rn(__fadd_rn(e0, e1), e2), e3);
        pi[0] = __fdiv_rn(e0, s); pi[1] = __fdiv_rn(e1, s);
        pi[2] = __fdiv_rn(e2, s); pi[3] = __fdiv_rn(e3, s);
    }

    float v0 = 0.f, v1 = 0.f;   // my two cells: lane, lane+32

#pragma unroll
    for (int a = 0; a < NANCH; ++a) {
        float fr[2]; int ai[2];
#pragma unroll
        for (int d = 0; d < 2; ++d) {
            const float x = L[a * 3 + d];
            float u = xla_sigmoidf(x);
            u = fminf(fmaxf(u, 1e-6f), 1.0f - 1e-6f);
            float p = __fmul_rn(u, 7.0f);
            p = fminf(p, 7.0f - 1e-6f);
            p = fmaxf(p, 0.f);
            int aa = (int)floorf(p);
            aa = max(0, min(aa, 6));
            float f = __fadd_rn(p, -(float)aa);
            f = fminf(fmaxf(f, 1e-6f), 1.0f - 1e-6f);
            fr[d] = f; ai[d] = aa;
        }
        const float om0 = __fadd_rn(1.0f, -fr[0]);
        const float om1 = __fadd_rn(1.0f, -fr[1]);
        float w[4];
        w[0] = __fmul_rn(om0,   om1);
        w[1] = __fmul_rn(fr[0], om1);
        w[2] = __fmul_rn(om0,   fr[1]);
        w[3] = __fmul_rn(fr[0], fr[1]);
        const float ws = __fadd_rn(__fadd_rn(__fadd_rn(w[0], w[1]), w[2]), w[3]);
        const float denom = __fadd_rn(ws, 1e-9f);
#pragma unroll
        for (int t = 0; t < 4; ++t) {
            const int c0 = ai[0] + (t & 1);
            const int c1 = ai[1] + ((t >> 1) & 1);
            const int idx = c0 + (c1 << 3);
            const float wv = __fmul_rn(__fdiv_rn(w[t], denom), pi[a]);
            if (idx == lane)      v0 = __fadd_rn(v0, wv);
            if (idx == lane + 32) v1 = __fadd_rn(v1, wv);
        }
    }

    // normalize by grid sum (common denominator: cannot flip ranks)
    float s = __fadd_rn(v0, v1);
    s = __fadd_rn(s, __shfl_xor_sync(0xffffffffu, s, 16));
    s = __fadd_rn(s, __shfl_xor_sync(0xffffffffu, s, 8));
    s = __fadd_rn(s, __shfl_xor_sync(0xffffffffu, s, 4));
    s = __fadd_rn(s, __shfl_xor_sync(0xffffffffu, s, 2));
    s = __fadd_rn(s, __shfl_xor_sync(0xffffffffu, s, 1));
    const float dn = __fadd_rn(s, 1e-9f);
    v0 = __fdiv_rn(v0, dn);
    v1 = __fdiv_rn(v1, dn);

    float* out_idx = out + (size_t)token * KOUT;
    float* out_w   = out + (size_t)NTOK * KOUT + (size_t)token * KOUT;

    for (int r = 0; r < KOUT; ++r) {
        unsigned long long k0 =
            ((unsigned long long)ford(v0) << 32) | (unsigned int)(63 - lane);
        unsigned long long k1 =
            ((unsigned long long)ford(v1) << 32) | (unsigned int)(63 - (lane + 32));
        unsigned long long k = (k0 > k1) ? k0 : k1;
#pragma unroll
        for (int sft = 16; sft > 0; sft >>= 1) {
            unsigned long long o = __shfl_xor_sync(0xffffffffu, k, sft);
            if (o > k) k = o;
        }
        const int cell = 63 - (int)(k & 63ull);
        const unsigned int ou = (unsigned int)(k >> 32);
        const float val =
            __uint_as_float((ou & 0x80000000u) ? (ou ^ 0x80000000u) : ~ou);
        if (lane == 0) {
            out_idx[r] = (float)cell;
            out_w[r]   = val;
        }
        if (cell == lane)      v0 = -1.0f;
        if (cell == lane + 32) v1 = -1.0f;
    }
}

// ---------------------------------------------------------------------------
extern "C" void kernel_launch(void* const* d_in, const int* in_sizes, int n_in,
                              void* d_out, int out_size) {
    const float* hidden = nullptr;
    const float* W = nullptr;
    const float* b = nullptr;
    for (int i = 0; i < n_in; ++i) {
        if (in_sizes[i] == NTOK * HDIM)      hidden = (const float*)d_in[i];
        else if (in_sizes[i] == NOUT * HDIM) W = (const float*)d_in[i];
        else if (in_sizes[i] == NOUT)        b = (const float*)d_in[i];
    }
    (void)out_size;

    cudaFuncSetAttribute(logits_chunk_kernel,
                         cudaFuncAttributeMaxDynamicSharedMemorySize, SMEM_TOTAL);
    dim3 grid(NTOK / TOKB, 2);
    logits_chunk_kernel<<<grid, TPB, SMEM_TOTAL>>>(hidden, W);
    route_kernel<<<NTOK / 8, 256>>>(b, (float*)d_out);
}